// round 13
// baseline (speedup 1.0000x reference)
#include <cuda_runtime.h>
#include <cuda_fp16.h>
#include <cstdint>

#define NT 4096   // tokens
#define DM 1024   // model dim
#define DF 4096   // ffn dim

// ---- scratch (static device globals; allowed) ----
__device__ __half g_Eh[(size_t)NT * DM];
__device__ __half g_QKVh[(size_t)NT * 3072];      // fused Q|K|V (half), stride 3072
__device__ float  g_S[(size_t)NT * NT];           // attention scores fp32
__device__ __half g_Sh[(size_t)NT * NT];          // softmax probs half
__device__ float  g_AE[NT * DM];
__device__ __half g_Xh[NT * DM];
__device__ __half g_Hh[(size_t)NT * DF];
__device__ __half g_Wqkvh[(size_t)DM * 3072];     // [1024][3072] half (n-major rows)
__device__ __half g_W1h[(size_t)DM * DF];         // [1024][4096] half
__device__ __half g_W2h[(size_t)DF * DM];         // [4096][1024] half
__device__ float  g_bqkv[3072];

__device__ __forceinline__ uint32_t smem_u32(const void* p) {
    uint32_t a;
    asm("{ .reg .u64 t; cvta.to.shared.u64 t, %1; cvt.u32.u64 %0, t; }" : "=r"(a) : "l"(p));
    return a;
}
__device__ __forceinline__ void mma_f16(float* c, const uint32_t* a, const uint32_t* b) {
    asm volatile(
        "mma.sync.aligned.m16n8k16.row.col.f32.f16.f16.f32 "
        "{%0,%1,%2,%3}, {%4,%5,%6,%7}, {%8,%9}, {%0,%1,%2,%3};"
        : "+f"(c[0]), "+f"(c[1]), "+f"(c[2]), "+f"(c[3])
        : "r"(a[0]), "r"(a[1]), "r"(a[2]), "r"(a[3]), "r"(b[0]), "r"(b[1]));
}
__device__ __forceinline__ void ldsm4(uint32_t& r0, uint32_t& r1, uint32_t& r2, uint32_t& r3,
                                      uint32_t addr) {
    asm volatile("ldmatrix.sync.aligned.m8n8.x4.shared.b16 {%0,%1,%2,%3}, [%4];"
                 : "=r"(r0), "=r"(r1), "=r"(r2), "=r"(r3) : "r"(addr));
}
__device__ __forceinline__ void ldsm4t(uint32_t& r0, uint32_t& r1, uint32_t& r2, uint32_t& r3,
                                       uint32_t addr) {
    asm volatile("ldmatrix.sync.aligned.m8n8.x4.trans.shared.b16 {%0,%1,%2,%3}, [%4];"
                 : "=r"(r0), "=r"(r1), "=r"(r2), "=r"(r3) : "r"(addr));
}

// ===========================================================================
// fp16 mma.sync GEMM (R8 core).  C = alpha * A @ B (+bias)(+relu).
//   TRB=0: B given as Bt[N][K] (K-major rows)  -- ldmatrix non-trans;
//          smem rows 32 half = 64B, swizzle c_phys = c ^ ((r>>1)&3)
//   TRB=1: B given as B[K][N]  (N-major rows)  -- ldmatrix.trans;
//          smem tile 32 k-rows x 256B, swizzle chunk c_phys = c ^ (r&7)
// Tiles 128x128x32, 256 threads = 8 warps (2 m-slabs x 4 n-slabs, 64x32).
// ===========================================================================
template <bool CAUSAL, bool TRIK, bool RELU, bool BIAS, bool HALF_OUT, bool TRB>
__global__ __launch_bounds__(256, 2)
void hgemm2(const __half* __restrict__ A, const __half* __restrict__ Bt,
            const float* __restrict__ bias, void* __restrict__ Cv,
            int N, int Kdim, int lda, int ldb, float alpha)
{
    __shared__ __align__(16) uint32_t As[2][2048];
    __shared__ __align__(16) uint32_t Bs[2][2048];

    const int bx = blockIdx.x, by = blockIdx.y;
    if (CAUSAL && bx > by) return;

    const int tid  = threadIdx.x;
    const int wid  = tid >> 5;
    const int lane = tid & 31;
    const int g    = lane >> 2;
    const int tig  = lane & 3;
    const int l7   = lane & 7;
    const int q    = lane >> 3;

    const int wmt = (wid & 1) * 4;
    const int wnt = (wid >> 1) * 4;

    int kEnd = Kdim;
    if (TRIK) { int lim = (by + 1) * 128; kEnd = lim < Kdim ? lim : Kdim; }
    const int niter = kEnd >> 5;

    // ---- copy-side mappings ----
    const int r0c = tid >> 2, c0c = tid & 3;
    const int wA0 = r0c * 16 + ((c0c ^ ((r0c >> 1) & 3)) << 2);
    const int r1c = r0c + 64;
    const int wA1 = r1c * 16 + ((c0c ^ ((r1c >> 1) & 3)) << 2);
    const __half* aG0 = A + (size_t)(by * 128 + r0c) * (size_t)lda + c0c * 8;
    const __half* aG1 = A + (size_t)(by * 128 + r1c) * (size_t)lda + c0c * 8;

    const __half* bG0 = TRB ? nullptr : Bt + (size_t)(bx * 128 + r0c) * (size_t)ldb + c0c * 8;
    const __half* bG1 = TRB ? nullptr : Bt + (size_t)(bx * 128 + r1c) * (size_t)ldb + c0c * 8;
    // TRB: tile = 32 k-rows x 128 n-halfs, 64 words (256B) per row
    const int rT0 = tid >> 4, cT = tid & 15;
    const int wB0 = TRB ? (rT0 * 64 + ((cT ^ (rT0 & 7)) << 2)) : wA0;
    const int wB1 = TRB ? ((rT0 + 16) * 64 + ((cT ^ ((rT0 + 16) & 7)) << 2)) : wA1;
    const __half* bT0 = TRB ? Bt + (size_t)rT0 * (size_t)ldb + bx * 128 + cT * 8 : nullptr;
    const __half* bT1 = TRB ? Bt + (size_t)(rT0 + 16) * (size_t)ldb + bx * 128 + cT * 8 : nullptr;

    uint4 ra0, ra1, rb0, rb1;
#define LDG_T(k0) do { \
        ra0 = *(const uint4*)(aG0 + (k0)); \
        ra1 = *(const uint4*)(aG1 + (k0)); \
        if (TRB) { \
            rb0 = *(const uint4*)(bT0 + (size_t)(k0) * (size_t)ldb); \
            rb1 = *(const uint4*)(bT1 + (size_t)(k0) * (size_t)ldb); \
        } else { \
            rb0 = *(const uint4*)(bG0 + (k0)); \
            rb1 = *(const uint4*)(bG1 + (k0)); \
        } } while (0)
#define STS_T(buf) do { \
        *(uint4*)&As[buf][wA0] = ra0; \
        *(uint4*)&As[buf][wA1] = ra1; \
        *(uint4*)&Bs[buf][wB0] = rb0; \
        *(uint4*)&Bs[buf][wB1] = rb1; \
    } while (0)

    const uint32_t aSm = smem_u32(As);
    const uint32_t bSm = smem_u32(Bs);

    uint32_t aOff[4][2], bOff[2][2];
#pragma unroll
    for (int m = 0; m < 4; m++) {
        int r = (wmt + m) * 16 + (q & 1) * 8 + l7;
#pragma unroll
        for (int ks = 0; ks < 2; ks++) {
            uint32_t c = (uint32_t)(2 * ks) + (uint32_t)(q >> 1);
            aOff[m][ks] = (uint32_t)r * 64u + ((c ^ ((uint32_t)(r >> 1) & 3u)) << 4);
        }
    }
#pragma unroll
    for (int p = 0; p < 2; p++) {
#pragma unroll
        for (int ks = 0; ks < 2; ks++) {
            if (TRB) {
                // stored tile row = k (256B/row), chunk = n
                uint32_t r = (uint32_t)(ks * 16 + (q & 1) * 8 + l7);
                uint32_t c = (uint32_t)(wnt + 2 * p + (q >> 1));
                bOff[p][ks] = r * 256u + ((c ^ (r & 7u)) << 4);   // FIX: 256B row stride
            } else {
                int r = (wnt + 2 * p + (q >> 1)) * 8 + l7;
                uint32_t c = (uint32_t)(2 * ks) + (uint32_t)(q & 1);
                bOff[p][ks] = (uint32_t)r * 64u + ((c ^ ((uint32_t)(r >> 1) & 3u)) << 4);
            }
        }
    }

    float acc[4][4][4];
#pragma unroll
    for (int i = 0; i < 4; i++)
#pragma unroll
        for (int j = 0; j < 4; j++)
#pragma unroll
            for (int t = 0; t < 4; t++) acc[i][j][t] = 0.f;

    LDG_T(0);
    STS_T(0);
    __syncthreads();

    for (int i = 0; i < niter; i++) {
        const int b = i & 1;
        if (i + 1 < niter) LDG_T((i + 1) * 32);

        const uint32_t aBase = aSm + (uint32_t)b * 8192u;
        const uint32_t bBase = bSm + (uint32_t)b * 8192u;
#pragma unroll
        for (int ks = 0; ks < 2; ks++) {
            uint32_t af[4][4], bf[4][2];
#pragma unroll
            for (int m = 0; m < 4; m++)
                ldsm4(af[m][0], af[m][1], af[m][2], af[m][3], aBase + aOff[m][ks]);
#pragma unroll
            for (int p = 0; p < 2; p++) {
                if (TRB)
                    ldsm4t(bf[2 * p][0], bf[2 * p][1], bf[2 * p + 1][0], bf[2 * p + 1][1],
                           bBase + bOff[p][ks]);
                else
                    ldsm4(bf[2 * p][0], bf[2 * p][1], bf[2 * p + 1][0], bf[2 * p + 1][1],
                          bBase + bOff[p][ks]);
            }
#pragma unroll
            for (int m = 0; m < 4; m++)
#pragma unroll
                for (int n = 0; n < 4; n++)
                    mma_f16(acc[m][n], af[m], bf[n]);
        }

        if (i + 1 < niter) STS_T(b ^ 1);
        __syncthreads();
    }

    // ---- epilogue ----
    const int rowBase = by * 128 + (wid & 1) * 64 + g;
    const int colBase = bx * 128 + (wid >> 1) * 32 + tig * 2;
#pragma unroll
    for (int m = 0; m < 4; m++) {
        const int r0 = rowBase + m * 16;
#pragma unroll
        for (int n = 0; n < 4; n++) {
            const int col = colBase + n * 8;
            float b0 = 0.f, b1 = 0.f;
            if (BIAS) { b0 = bias[col]; b1 = bias[col + 1]; }
            float v0x = acc[m][n][0] * alpha + b0;
            float v0y = acc[m][n][1] * alpha + b1;
            float v1x = acc[m][n][2] * alpha + b0;
            float v1y = acc[m][n][3] * alpha + b1;
            if (RELU) {
                v0x = fmaxf(v0x, 0.f); v0y = fmaxf(v0y, 0.f);
                v1x = fmaxf(v1x, 0.f); v1y = fmaxf(v1y, 0.f);
            }
            if (HALF_OUT) {
                __half* C = (__half*)Cv;
                *(__half2*)(C + (size_t)r0 * N + col)       = __floats2half2_rn(v0x, v0y);
                *(__half2*)(C + (size_t)(r0 + 8) * N + col) = __floats2half2_rn(v1x, v1y);
            } else {
                float* C = (float*)Cv;
                *(float2*)(C + (size_t)r0 * N + col)       = make_float2(v0x, v0y);
                *(float2*)(C + (size_t)(r0 + 8) * N + col) = make_float2(v1x, v1y);
            }
        }
    }
#undef LDG_T
#undef STS_T
}

// ===========================================================================
// Merged streaming prologue (no smem, no transposes):
//   [0, 4096)       : f2h E                      (1M float4)
//   [4096, 7168)    : Wq|Wk|Wv -> Wqkvh [1024][3072] (n-concat, f2h)
//   [7168, 11264)   : f2h W1 flat -> W1h [1024][4096]
//   [11264, 15360)  : f2h W2 flat -> W2h [4096][1024]
//   [15360, 15372)  : bias concat
// ===========================================================================
__global__ __launch_bounds__(256)
void prep(const float* __restrict__ E,
          const float* __restrict__ Wq, const float* __restrict__ Wk,
          const float* __restrict__ Wv,
          const float* __restrict__ W1, const float* __restrict__ W2,
          const float* __restrict__ bq, const float* __restrict__ bk,
          const float* __restrict__ bv,
          __half* __restrict__ Eh, __half* __restrict__ Wqkvh,
          __half* __restrict__ W1h, __half* __restrict__ W2h,
          float* __restrict__ bqkv)
{
    const int bid = blockIdx.x;
    const int tid = threadIdx.x;

    if (bid < 4096) {                         // f2h E
        int i = bid * 256 + tid;
        float4 v = ((const float4*)E)[i];
        ((__half2*)Eh)[i * 2]     = __floats2half2_rn(v.x, v.y);
        ((__half2*)Eh)[i * 2 + 1] = __floats2half2_rn(v.z, v.w);
    } else if (bid < 7168) {                  // Wq/Wk/Wv n-concat f2h
        int t = bid - 4096;
        int which = t >> 10;                  // 0..2
        int tt = t & 1023;                    // k row
        const float* src = (which == 0) ? Wq : (which == 1) ? Wk : Wv;
        float4 v = ((const float4*)(src + (size_t)tt * DM))[tid];   // n = tid*4
        __half2* dst = (__half2*)(Wqkvh + (size_t)tt * 3072 + which * 1024 + tid * 4);
        dst[0] = __floats2half2_rn(v.x, v.y);
        dst[1] = __floats2half2_rn(v.z, v.w);
    } else if (bid < 11264) {                 // W1 flat f2h (4M elems)
        int i = (bid - 7168) * 256 + tid;
        float4 v = ((const float4*)W1)[i];
        ((__half2*)W1h)[i * 2]     = __floats2half2_rn(v.x, v.y);
        ((__half2*)W1h)[i * 2 + 1] = __floats2half2_rn(v.z, v.w);
    } else if (bid < 15360) {                 // W2 flat f2h
        int i = (bid - 11264) * 256 + tid;
        float4 v = ((const float4*)W2)[i];
        ((__half2*)W2h)[i * 2]     = __floats2half2_rn(v.x, v.y);
        ((__half2*)W2h)[i * 2 + 1] = __floats2half2_rn(v.z, v.w);
    } else {                                  // bias concat
        int i = (bid - 15360) * 256 + tid;
        float v = (i < 1024) ? bq[i] : (i < 2048) ? bk[i - 1024] : bv[i - 2048];
        bqkv[i] = v;
    }
}

// ============ fast exp (FMA pipe) ============
__device__ __forceinline__ float fast_exp(float x) {
    float y = x * 1.4426950408889634f;
    float n = rintf(y);
    float f = y - n;
    float p = 1.5403530393e-4f;
    p = fmaf(p, f, 1.3333558146e-3f);
    p = fmaf(p, f, 9.6181291076e-3f);
    p = fmaf(p, f, 5.5504108665e-2f);
    p = fmaf(p, f, 2.4022650696e-1f);
    p = fmaf(p, f, 6.9314718056e-1f);
    p = fmaf(p, f, 1.0f);
    float ec = fmaxf(n, -126.f);
    return __int_as_float(((int)ec + 127) << 23) * p;
}

// ============ causal softmax: fp32 scores -> fp16 probs (zero-padded) ============
__global__ void softmax_causal(const float* __restrict__ S, __half* __restrict__ Sh)
{
    const int r = blockIdx.x;
    const int tid = threadIdx.x;
    const int limit = ((r >> 7) + 1) << 7;
    const float* row = S + (size_t)r * NT;
    __half* rowh = Sh + (size_t)r * NT;

    float vals[16];
    int n = 0;
    float m = -1e30f;
    for (int j = tid; j < limit; j += 256) {
        float v = (j <= r) ? row[j] : -1e30f;
        vals[n++] = v;
        m = fmaxf(m, v);
    }
    __shared__ float redm[8], reds[8];
#pragma unroll
    for (int o = 16; o > 0; o >>= 1) m = fmaxf(m, __shfl_xor_sync(0xffffffffu, m, o));
    if ((tid & 31) == 0) redm[tid >> 5] = m;
    __syncthreads();
    m = redm[0];
#pragma unroll
    for (int i = 1; i < 8; i++) m = fmaxf(m, redm[i]);

    float s = 0.f;
    for (int i = 0; i < n; i++) { float e = fast_exp(vals[i] - m); vals[i] = e; s += e; }
#pragma unroll
    for (int o = 16; o > 0; o >>= 1) s += __shfl_xor_sync(0xffffffffu, s, o);
    if ((tid & 31) == 0) reds[tid >> 5] = s;
    __syncthreads();
    s = reds[0];
#pragma unroll
    for (int i = 1; i < 8; i++) s += reds[i];

    const float inv = 1.f / s;
    n = 0;
    for (int j = tid; j < limit; j += 256) rowh[j] = __float2half(vals[n++] * inv);
}

// ============ add + LayerNorm -> fp16 X ============
__global__ void add_layernorm(const float* __restrict__ AE, const float* __restrict__ E,
                              const float* __restrict__ gamma, const float* __restrict__ beta,
                              __half* __restrict__ X)
{
    const int r = blockIdx.x;
    const int tid = threadIdx.x;
    float4 a = ((const float4*)(AE + (size_t)r * DM))[tid];
    float4 e = ((const float4*)(E + (size_t)r * DM))[tid];
    float x0 = a.x + e.x, x1 = a.y + e.y, x2 = a.z + e.z, x3 = a.w + e.w;
    float s = x0 + x1 + x2 + x3;
    float q = x0 * x0 + x1 * x1 + x2 * x2 + x3 * x3;
    __shared__ float rs[8], rq[8];
#pragma unroll
    for (int o = 16; o > 0; o >>= 1) {
        s += __shfl_xor_sync(0xffffffffu, s, o);
        q += __shfl_xor_sync(0xffffffffu, q, o);
    }
    if ((tid & 31) == 0) { rs[tid >> 5] = s; rq[tid >> 5] = q; }
    __syncthreads();
    s = rs[0]; q = rq[0];
#pragma unroll
    for (int i = 1; i < 8; i++) { s += rs[i]; q += rq[i]; }
    const float mean = s * (1.f / DM);
    const float var  = q * (1.f / DM) - mean * mean;
    const float inv  = rsqrtf(var + 1e-5f);
    float4 gg = ((const float4*)gamma)[tid];
    float4 bb = ((const float4*)beta)[tid];
    __half2 o0 = __floats2half2_rn((x0 - mean) * inv * gg.x + bb.x,
                                   (x1 - mean) * inv * gg.y + bb.y);
    __half2 o1 = __floats2half2_rn((x2 - mean) * inv * gg.z + bb.z,
                                   (x3 - mean) * inv * gg.w + bb.w);
    ((__half2*)(X + (size_t)r * DM))[tid * 2]     = o0;
    ((__half2*)(X + (size_t)r * DM))[tid * 2 + 1] = o1;
}

// ============ launch ============
extern "C" void kernel_launch(void* const* d_in, const int* in_sizes, int n_in,
                              void* d_out, int out_size)
{
    (void)in_sizes; (void)n_in; (void)out_size;
    const float* E     = (const float*)d_in[0];
    const float* Wq    = (const float*)d_in[1];
    const float* bq    = (const float*)d_in[2];
    const float* Wk    = (const float*)d_in[3];
    const float* bk    = (const float*)d_in[4];
    const float* Wv    = (const float*)d_in[5];
    const float* bv    = (const float*)d_in[6];
    const float* gamma = (const float*)d_in[7];
    const float* beta  = (const float*)d_in[8];
    const float* W1    = (const float*)d_in[9];
    const float* b1    = (const float*)d_in[10];
    const float* W2    = (const float*)d_in[11];
    const float* b2    = (const float*)d_in[12];
    float* out = (float*)d_out;

    __half *Eh, *QKVh, *Sh, *Xh, *Hh, *Wqkvh, *W1h, *W2h;
    float *S, *AE, *bqkv;
    cudaGetSymbolAddress((void**)&Eh,    g_Eh);
    cudaGetSymbolAddress((void**)&QKVh,  g_QKVh);
    cudaGetSymbolAddress((void**)&S,     g_S);
    cudaGetSymbolAddress((void**)&Sh,    g_Sh);
    cudaGetSymbolAddress((void**)&AE,    g_AE);
    cudaGetSymbolAddress((void**)&Xh,    g_Xh);
    cudaGetSymbolAddress((void**)&Hh,    g_Hh);
    cudaGetSymbolAddress((void**)&Wqkvh, g_Wqkvh);
    cudaGetSymbolAddress((void**)&W1h,   g_W1h);
    cudaGetSymbolAddress((void**)&W2h,   g_W2h);
    cudaGetSymbolAddress((void**)&bqkv,  g_bqkv);

    // merged streaming prologue
    prep<<<15372, 256>>>(E, Wq, Wk, Wv, W1, W2, bq, bk, bv,
                         Eh, Wqkvh, W1h, W2h, bqkv);

    dim3 blk(256);

    // fused QKV projection: B = Wqkvh [1024][3072]  (TRB)
    hgemm2<false, false, false, true, true, true><<<dim3(3072 / 128, NT / 128), blk>>>(
        Eh, Wqkvh, bqkv, QKVh, 3072, DM, DM, 3072, 1.f);

    // S = Q @ K^T / 32 (causal lower blocks): B = K rows (K-major, non-TRB)
    hgemm2<true, false, false, false, false, false><<<dim3(NT / 128, NT / 128), blk>>>(
        QKVh, QKVh + 1024, nullptr, S, NT, DM, 3072, 3072, 0.03125f);

    softmax_causal<<<NT, 256>>>(S, Sh);

    // AE = probs @ V (triangular K): B = V region [k=token][n=d] (TRB)
    hgemm2<false, true, false, false, false, true><<<dim3(DM / 128, NT / 128), blk>>>(
        Sh, QKVh + 2048, nullptr, AE, DM, NT, NT, 3072, 1.f);

    add_layernorm<<<NT, 256>>>(AE, E, gamma, beta, Xh);

    // FFN: B = W1h [1024][4096], W2h [4096][1024]  (TRB)
    hgemm2<false, false, true, true, true, true><<<dim3(DF / 128, NT / 128), blk>>>(
        Xh, W1h, b1, Hh, DF, DM, DM, DF, 1.f);
    hgemm2<false, false, false, true, false, true><<<dim3(DM / 128, NT / 128), blk>>>(
        Hh, W2h, b2, out, DM, DF, DF, DM, 1.f);
}

// round 14
// speedup vs baseline: 1.4946x; 1.4946x over previous
#include <cuda_runtime.h>
#include <cuda_fp16.h>
#include <cstdint>

#define NT 4096   // tokens
#define DM 1024   // model dim
#define DF 4096   // ffn dim

// ---- scratch (static device globals; allowed) ----
__device__ __half g_Eh[(size_t)NT * DM];
__device__ __half g_QKVh[(size_t)NT * 3072];      // fused Q|K|V (half), stride 3072
__device__ float  g_S[(size_t)NT * NT];           // attention scores fp32
__device__ __half g_Sh[(size_t)NT * NT];          // softmax probs half
__device__ float  g_AE[NT * DM];
__device__ __half g_Xh[NT * DM];
__device__ __half g_Hh[(size_t)NT * DF];
__device__ __half g_Wqkvth[3072 * DM];            // [3072][1024] W^T half
__device__ __half g_W1th[(size_t)DF * DM];        // [4096][1024]
__device__ __half g_W2th[(size_t)DM * DF];        // [1024][4096]
__device__ __half g_Vth[(size_t)DM * NT];         // [1024][4096] V^T half
__device__ float  g_bqkv[3072];

__device__ __forceinline__ uint32_t smem_u32(const void* p) {
    uint32_t a;
    asm("{ .reg .u64 t; cvta.to.shared.u64 t, %1; cvt.u32.u64 %0, t; }" : "=r"(a) : "l"(p));
    return a;
}
__device__ __forceinline__ void mma_f16(float* c, const uint32_t* a, const uint32_t* b) {
    asm volatile(
        "mma.sync.aligned.m16n8k16.row.col.f32.f16.f16.f32 "
        "{%0,%1,%2,%3}, {%4,%5,%6,%7}, {%8,%9}, {%0,%1,%2,%3};"
        : "+f"(c[0]), "+f"(c[1]), "+f"(c[2]), "+f"(c[3])
        : "r"(a[0]), "r"(a[1]), "r"(a[2]), "r"(a[3]), "r"(b[0]), "r"(b[1]));
}
__device__ __forceinline__ void ldsm4(uint32_t& r0, uint32_t& r1, uint32_t& r2, uint32_t& r3,
                                      uint32_t addr) {
    asm volatile("ldmatrix.sync.aligned.m8n8.x4.shared.b16 {%0,%1,%2,%3}, [%4];"
                 : "=r"(r0), "=r"(r1), "=r"(r2), "=r"(r3) : "r"(addr));
}

// ===========================================================================
// fp16 mma.sync GEMM — EXACT R8/R11 configuration (proven fastest; GEMMs sit
// at the legacy-HMMA ceiling ~0.5 HMMA/cyc/SM). Do not touch.
// ===========================================================================
template <bool CAUSAL, bool TRIK, bool RELU, bool BIAS, bool HALF_OUT>
__global__ __launch_bounds__(256, 2)
void hgemm2(const __half* __restrict__ A, const __half* __restrict__ Bt,
            const float* __restrict__ bias, void* __restrict__ Cv,
            int N, int Kdim, int lda, int ldb, float alpha)
{
    __shared__ __align__(16) uint32_t As[2][2048];
    __shared__ __align__(16) uint32_t Bs[2][2048];

    const int bx = blockIdx.x, by = blockIdx.y;
    if (CAUSAL && bx > by) return;

    const int tid  = threadIdx.x;
    const int wid  = tid >> 5;
    const int lane = tid & 31;
    const int g    = lane >> 2;
    const int tig  = lane & 3;
    const int l7   = lane & 7;
    const int q    = lane >> 3;

    const int wmt = (wid & 1) * 4;
    const int wnt = (wid >> 1) * 4;

    int kEnd = Kdim;
    if (TRIK) { int lim = (by + 1) * 128; kEnd = lim < Kdim ? lim : Kdim; }
    const int niter = kEnd >> 5;

    const int r0c = tid >> 2, c0c = tid & 3;
    const int w0 = r0c * 16 + ((c0c ^ ((r0c >> 1) & 3)) << 2);
    const int r1c = r0c + 64;
    const int w1 = r1c * 16 + ((c0c ^ ((r1c >> 1) & 3)) << 2);
    const __half* aG0 = A  + (size_t)(by * 128 + r0c) * (size_t)lda + c0c * 8;
    const __half* aG1 = A  + (size_t)(by * 128 + r1c) * (size_t)lda + c0c * 8;
    const __half* bG0 = Bt + (size_t)(bx * 128 + r0c) * (size_t)ldb + c0c * 8;
    const __half* bG1 = Bt + (size_t)(bx * 128 + r1c) * (size_t)ldb + c0c * 8;

    uint4 ra0, ra1, rb0, rb1;
#define LDG_T(k0) do { \
        ra0 = *(const uint4*)(aG0 + (k0)); \
        ra1 = *(const uint4*)(aG1 + (k0)); \
        rb0 = *(const uint4*)(bG0 + (k0)); \
        rb1 = *(const uint4*)(bG1 + (k0)); \
    } while (0)
#define STS_T(buf) do { \
        *(uint4*)&As[buf][w0] = ra0; \
        *(uint4*)&As[buf][w1] = ra1; \
        *(uint4*)&Bs[buf][w0] = rb0; \
        *(uint4*)&Bs[buf][w1] = rb1; \
    } while (0)

    const uint32_t aSm = smem_u32(As);
    const uint32_t bSm = smem_u32(Bs);

    uint32_t aOff[4][2], bOff[2][2];
#pragma unroll
    for (int m = 0; m < 4; m++) {
        int r = (wmt + m) * 16 + (q & 1) * 8 + l7;
#pragma unroll
        for (int ks = 0; ks < 2; ks++) {
            uint32_t c = (uint32_t)(2 * ks) + (uint32_t)(q >> 1);
            aOff[m][ks] = (uint32_t)r * 64u + ((c ^ ((uint32_t)(r >> 1) & 3u)) << 4);
        }
    }
#pragma unroll
    for (int p = 0; p < 2; p++) {
        int r = (wnt + 2 * p + (q >> 1)) * 8 + l7;
#pragma unroll
        for (int ks = 0; ks < 2; ks++) {
            uint32_t c = (uint32_t)(2 * ks) + (uint32_t)(q & 1);
            bOff[p][ks] = (uint32_t)r * 64u + ((c ^ ((uint32_t)(r >> 1) & 3u)) << 4);
        }
    }

    float acc[4][4][4];
#pragma unroll
    for (int i = 0; i < 4; i++)
#pragma unroll
        for (int j = 0; j < 4; j++)
#pragma unroll
            for (int t = 0; t < 4; t++) acc[i][j][t] = 0.f;

    LDG_T(0);
    STS_T(0);
    __syncthreads();

    for (int i = 0; i < niter; i++) {
        const int b = i & 1;
        if (i + 1 < niter) LDG_T((i + 1) * 32);

        const uint32_t aBase = aSm + (uint32_t)b * 8192u;
        const uint32_t bBase = bSm + (uint32_t)b * 8192u;
#pragma unroll
        for (int ks = 0; ks < 2; ks++) {
            uint32_t af[4][4], bf[4][2];
#pragma unroll
            for (int m = 0; m < 4; m++)
                ldsm4(af[m][0], af[m][1], af[m][2], af[m][3], aBase + aOff[m][ks]);
#pragma unroll
            for (int p = 0; p < 2; p++)
                ldsm4(bf[2 * p][0], bf[2 * p][1], bf[2 * p + 1][0], bf[2 * p + 1][1],
                      bBase + bOff[p][ks]);
#pragma unroll
            for (int m = 0; m < 4; m++)
#pragma unroll
                for (int n = 0; n < 4; n++)
                    mma_f16(acc[m][n], af[m], bf[n]);
        }

        if (i + 1 < niter) STS_T(b ^ 1);
        __syncthreads();
    }

    // ---- epilogue ----
    const int rowBase = by * 128 + (wid & 1) * 64 + g;
    const int colBase = bx * 128 + (wid >> 1) * 32 + tig * 2;
#pragma unroll
    for (int m = 0; m < 4; m++) {
        const int r0 = rowBase + m * 16;
#pragma unroll
        for (int n = 0; n < 4; n++) {
            const int col = colBase + n * 8;
            float b0 = 0.f, b1 = 0.f;
            if (BIAS) { b0 = bias[col]; b1 = bias[col + 1]; }
            float v0x = acc[m][n][0] * alpha + b0;
            float v0y = acc[m][n][1] * alpha + b1;
            float v1x = acc[m][n][2] * alpha + b0;
            float v1y = acc[m][n][3] * alpha + b1;
            if (RELU) {
                v0x = fmaxf(v0x, 0.f); v0y = fmaxf(v0y, 0.f);
                v1x = fmaxf(v1x, 0.f); v1y = fmaxf(v1y, 0.f);
            }
            if (HALF_OUT) {
                __half* C = (__half*)Cv;
                *(__half2*)(C + (size_t)r0 * N + col)       = __floats2half2_rn(v0x, v0y);
                *(__half2*)(C + (size_t)(r0 + 8) * N + col) = __floats2half2_rn(v1x, v1y);
            } else {
                float* C = (float*)Cv;
                *(float2*)(C + (size_t)r0 * N + col)       = make_float2(v0x, v0y);
                *(float2*)(C + (size_t)(r0 + 8) * N + col) = make_float2(v1x, v1y);
            }
        }
    }
#undef LDG_T
#undef STS_T
}

// ===========================================================================
// Merged prologue (R11): ONE launch does f2h(E), weight transposes, bias cat.
// ===========================================================================
__device__ __forceinline__ void tile_transpose_f2h(
    const float* __restrict__ in, __half* __restrict__ out,
    int inS, int outS, int bcx, int bry, int tid)
{
    __shared__ float t[32][33];
    const int x = tid & 31, y = tid >> 5;
    const int bc = bcx * 32, br = bry * 32;
#pragma unroll
    for (int j = 0; j < 32; j += 8)
        t[y + j][x] = in[(size_t)(br + y + j) * inS + bc + x];
    __syncthreads();
#pragma unroll
    for (int j = 0; j < 32; j += 8)
        out[(size_t)(bc + y + j) * outS + br + x] = __float2half(t[x][y + j]);
}

__global__ __launch_bounds__(256)
void prep(const float* __restrict__ E,
          const float* __restrict__ Wq, const float* __restrict__ Wk,
          const float* __restrict__ Wv,
          const float* __restrict__ W1, const float* __restrict__ W2,
          const float* __restrict__ bq, const float* __restrict__ bk,
          const float* __restrict__ bv,
          __half* __restrict__ Eh, __half* __restrict__ Wqkvth,
          __half* __restrict__ W1th, __half* __restrict__ W2th,
          float* __restrict__ bqkv)
{
    const int bid = blockIdx.x;
    const int tid = threadIdx.x;

    if (bid < 4096) {                         // f2h E
        int i = bid * 256 + tid;
        float4 v = ((const float4*)E)[i];
        ((__half2*)Eh)[i * 2]     = __floats2half2_rn(v.x, v.y);
        ((__half2*)Eh)[i * 2 + 1] = __floats2half2_rn(v.z, v.w);
    } else if (bid < 7168) {                  // QKV weight transposes
        int t = bid - 4096;
        int which = t >> 10;
        int tt = t & 1023;
        const float* src = (which == 0) ? Wq : (which == 1) ? Wk : Wv;
        __half* dst = Wqkvth + (size_t)which * 1024 * DM;
        tile_transpose_f2h(src, dst, DM, DM, tt & 31, tt >> 5, tid);
    } else if (bid < 11264) {                 // W1 [1024,4096] -> W1th [4096,1024]
        int t = bid - 7168;
        tile_transpose_f2h(W1, W1th, DF, DM, t & 127, t >> 7, tid);
    } else if (bid < 15360) {                 // W2 [4096,1024] -> W2th [1024,4096]
        int t = bid - 11264;
        tile_transpose_f2h(W2, W2th, DM, DF, t & 31, t >> 5, tid);
    } else {                                  // bias concat
        int i = (bid - 15360) * 256 + tid;
        float v = (i < 1024) ? bq[i] : (i < 2048) ? bk[i - 1024] : bv[i - 2048];
        bqkv[i] = v;
    }
}

// ============ transpose fp16 -> fp16 (Vth) ============
__global__ void transpose_h2h(const __half* __restrict__ in, __half* __restrict__ out,
                              int inS, int outS)
{
    __shared__ __half t[32][34];
    const int bc = blockIdx.x * 32;
    const int br = blockIdx.y * 32;
    const int x = threadIdx.x, y = threadIdx.y;
#pragma unroll
    for (int j = 0; j < 32; j += 8)
        t[y + j][x] = in[(size_t)(br + y + j) * inS + bc + x];
    __syncthreads();
#pragma unroll
    for (int j = 0; j < 32; j += 8)
        out[(size_t)(bc + y + j) * outS + br + x] = t[x][y + j];
}

// ============ fast exp (FMA pipe) ============
__device__ __forceinline__ float fast_exp(float x) {
    float y = x * 1.4426950408889634f;
    float n = rintf(y);
    float f = y - n;
    float p = 1.5403530393e-4f;
    p = fmaf(p, f, 1.3333558146e-3f);
    p = fmaf(p, f, 9.6181291076e-3f);
    p = fmaf(p, f, 5.5504108665e-2f);
    p = fmaf(p, f, 2.4022650696e-1f);
    p = fmaf(p, f, 6.9314718056e-1f);
    p = fmaf(p, f, 1.0f);
    float ec = fmaxf(n, -126.f);
    return __int_as_float(((int)ec + 127) << 23) * p;
}

// ===========================================================================
// Causal softmax, register-resident: 4 float4 chunks per thread, uniform
// per-block chunk guards (limit is constant within a block). No local-memory
// spills, 16B coalesced loads, __half2 stores. Writes [0, limit) per row,
// which is exactly what the triangular-K AV GEMM reads.
// ===========================================================================
__global__ void softmax_causal(const float* __restrict__ S, __half* __restrict__ Sh)
{
    const int r = blockIdx.x;
    const int tid = threadIdx.x;
    const int limit = ((r >> 7) + 1) << 7;        // multiple of 128, uniform per block
    const int nc = (limit + 1023) >> 10;          // active 1024-wide chunks (1..4)
    const float* row = S + (size_t)r * NT;
    __half* rowh = Sh + (size_t)r * NT;

    float4 v[4];
    float m = -1e30f;
#pragma unroll
    for (int i = 0; i < 4; i++) {
        if (i < nc) {
            const int j = i * 1024 + tid * 4;
            float4 t = *(const float4*)(row + j);
            t.x = (j     <= r) ? t.x : -1e30f;
            t.y = (j + 1 <= r) ? t.y : -1e30f;
            t.z = (j + 2 <= r) ? t.z : -1e30f;
            t.w = (j + 3 <= r) ? t.w : -1e30f;
            v[i] = t;
            m = fmaxf(m, fmaxf(fmaxf(t.x, t.y), fmaxf(t.z, t.w)));
        }
    }

    __shared__ float redm[8], reds[8];
#pragma unroll
    for (int o = 16; o > 0; o >>= 1) m = fmaxf(m, __shfl_xor_sync(0xffffffffu, m, o));
    if ((tid & 31) == 0) redm[tid >> 5] = m;
    __syncthreads();
    m = redm[0];
#pragma unroll
    for (int i = 1; i < 8; i++) m = fmaxf(m, redm[i]);

    float s = 0.f;
#pragma unroll
    for (int i = 0; i < 4; i++) {
        if (i < nc) {
            v[i].x = fast_exp(v[i].x - m);
            v[i].y = fast_exp(v[i].y - m);
            v[i].z = fast_exp(v[i].z - m);
            v[i].w = fast_exp(v[i].w - m);
            s += (v[i].x + v[i].y) + (v[i].z + v[i].w);
        }
    }
#pragma unroll
    for (int o = 16; o > 0; o >>= 1) s += __shfl_xor_sync(0xffffffffu, s, o);
    if ((tid & 31) == 0) reds[tid >> 5] = s;
    __syncthreads();
    s = reds[0];
#pragma unroll
    for (int i = 1; i < 8; i++) s += reds[i];

    const float inv = 1.f / s;
#pragma unroll
    for (int i = 0; i < 4; i++) {
        if (i < nc) {
            const int j = i * 1024 + tid * 4;
            *(__half2*)(rowh + j)     = __floats2half2_rn(v[i].x * inv, v[i].y * inv);
            *(__half2*)(rowh + j + 2) = __floats2half2_rn(v[i].z * inv, v[i].w * inv);
        }
    }
}

// ============ add + LayerNorm -> fp16 X ============
__global__ void add_layernorm(const float* __restrict__ AE, const float* __restrict__ E,
                              const float* __restrict__ gamma, const float* __restrict__ beta,
                              __half* __restrict__ X)
{
    const int r = blockIdx.x;
    const int tid = threadIdx.x;
    float4 a = ((const float4*)(AE + (size_t)r * DM))[tid];
    float4 e = ((const float4*)(E + (size_t)r * DM))[tid];
    float x0 = a.x + e.x, x1 = a.y + e.y, x2 = a.z + e.z, x3 = a.w + e.w;
    float s = x0 + x1 + x2 + x3;
    float q = x0 * x0 + x1 * x1 + x2 * x2 + x3 * x3;
    __shared__ float rs[8], rq[8];
#pragma unroll
    for (int o = 16; o > 0; o >>= 1) {
        s += __shfl_xor_sync(0xffffffffu, s, o);
        q += __shfl_xor_sync(0xffffffffu, q, o);
    }
    if ((tid & 31) == 0) { rs[tid >> 5] = s; rq[tid >> 5] = q; }
    __syncthreads();
    s = rs[0]; q = rq[0];
#pragma unroll
    for (int i = 1; i < 8; i++) { s += rs[i]; q += rq[i]; }
    const float mean = s * (1.f / DM);
    const float var  = q * (1.f / DM) - mean * mean;
    const float inv  = rsqrtf(var + 1e-5f);
    float4 gg = ((const float4*)gamma)[tid];
    float4 bb = ((const float4*)beta)[tid];
    __half2 o0 = __floats2half2_rn((x0 - mean) * inv * gg.x + bb.x,
                                   (x1 - mean) * inv * gg.y + bb.y);
    __half2 o1 = __floats2half2_rn((x2 - mean) * inv * gg.z + bb.z,
                                   (x3 - mean) * inv * gg.w + bb.w);
    ((__half2*)(X + (size_t)r * DM))[tid * 2]     = o0;
    ((__half2*)(X + (size_t)r * DM))[tid * 2 + 1] = o1;
}

// ============ launch ============
extern "C" void kernel_launch(void* const* d_in, const int* in_sizes, int n_in,
                              void* d_out, int out_size)
{
    (void)in_sizes; (void)n_in; (void)out_size;
    const float* E     = (const float*)d_in[0];
    const float* Wq    = (const float*)d_in[1];
    const float* bq    = (const float*)d_in[2];
    const float* Wk    = (const float*)d_in[3];
    const float* bk    = (const float*)d_in[4];
    const float* Wv    = (const float*)d_in[5];
    const float* bv    = (const float*)d_in[6];
    const float* gamma = (const float*)d_in[7];
    const float* beta  = (const float*)d_in[8];
    const float* W1    = (const float*)d_in[9];
    const float* b1    = (const float*)d_in[10];
    const float* W2    = (const float*)d_in[11];
    const float* b2    = (const float*)d_in[12];
    float* out = (float*)d_out;

    __half *Eh, *QKVh, *Sh, *Xh, *Hh, *Wqkvth, *W1th, *W2th, *Vth;
    float *S, *AE, *bqkv;
    cudaGetSymbolAddress((void**)&Eh,     g_Eh);
    cudaGetSymbolAddress((void**)&QKVh,   g_QKVh);
    cudaGetSymbolAddress((void**)&S,      g_S);
    cudaGetSymbolAddress((void**)&Sh,     g_Sh);
    cudaGetSymbolAddress((void**)&AE,     g_AE);
    cudaGetSymbolAddress((void**)&Xh,     g_Xh);
    cudaGetSymbolAddress((void**)&Hh,     g_Hh);
    cudaGetSymbolAddress((void**)&Wqkvth, g_Wqkvth);
    cudaGetSymbolAddress((void**)&W1th,   g_W1th);
    cudaGetSymbolAddress((void**)&W2th,   g_W2th);
    cudaGetSymbolAddress((void**)&Vth,    g_Vth);
    cudaGetSymbolAddress((void**)&bqkv,   g_bqkv);

    // ONE merged prologue launch
    prep<<<15372, 256>>>(E, Wq, Wk, Wv, W1, W2, bq, bk, bv,
                         Eh, Wqkvth, W1th, W2th, bqkv);

    dim3 blk(256);
    dim3 tb(32, 8);

    // fused QKV projection -> half [4096, 3072]
    hgemm2<false, false, false, true, true><<<dim3(3072 / 128, NT / 128), blk>>>(
        Eh, Wqkvth, bqkv, QKVh, 3072, DM, DM, DM, 1.f);

    // Vth[d][t] = V[t][d]
    transpose_h2h<<<dim3(DM / 32, NT / 32), tb>>>(QKVh + 2048, Vth, 3072, NT);

    // S = Q @ K^T / 32 (causal lower blocks) -> fp32
    hgemm2<true, false, false, false, false><<<dim3(NT / 128, NT / 128), blk>>>(
        QKVh, QKVh + 1024, nullptr, S, NT, DM, 3072, 3072, 0.03125f);

    softmax_causal<<<NT, 256>>>(S, Sh);

    // AE = probs @ V (triangular K) -> fp32
    hgemm2<false, true, false, false, false><<<dim3(DM / 128, NT / 128), blk>>>(
        Sh, Vth, nullptr, AE, DM, NT, NT, NT, 1.f);

    add_layernorm<<<NT, 256>>>(AE, E, gamma, beta, Xh);

    // FFN
    hgemm2<false, false, true, true, true><<<dim3(DF / 128, NT / 128), blk>>>(
        Xh, W1th, b1, Hh, DF, DM, DM, DM, 1.f);
    hgemm2<false, false, false, true, false><<<dim3(DM / 128, NT / 128), blk>>>(
        Hh, W2th, b2, out, DM, DF, DF, DF, 1.f);
}

// round 15
// speedup vs baseline: 1.5139x; 1.0129x over previous
#include <cuda_runtime.h>
#include <cuda_fp16.h>
#include <cstdint>

#define NT 4096   // tokens
#define DM 1024   // model dim
#define DF 4096   // ffn dim

// ---- scratch (static device globals; allowed) ----
__device__ __half g_Eh[(size_t)NT * DM];
__device__ __half g_QKVh[(size_t)NT * 3072];      // fused Q|K|V (half), stride 3072
__device__ float  g_S[(size_t)NT * NT];           // attention scores fp32
__device__ __half g_Sh[(size_t)NT * NT];          // softmax probs half
__device__ float  g_AE[NT * DM];                  // AV partial 0
__device__ float  g_AE2[NT * DM];                 // AV partial 1
__device__ __half g_Xh[NT * DM];
__device__ __half g_Hh[(size_t)NT * DF];
__device__ __half g_Wqkvth[3072 * DM];            // [3072][1024] W^T half
__device__ __half g_W1th[(size_t)DF * DM];        // [4096][1024]
__device__ __half g_W2th[(size_t)DM * DF];        // [1024][4096]
__device__ __half g_Vth[(size_t)DM * NT];         // [1024][4096] V^T half
__device__ float  g_bqkv[3072];

__device__ __forceinline__ uint32_t smem_u32(const void* p) {
    uint32_t a;
    asm("{ .reg .u64 t; cvta.to.shared.u64 t, %1; cvt.u32.u64 %0, t; }" : "=r"(a) : "l"(p));
    return a;
}
__device__ __forceinline__ void mma_f16(float* c, const uint32_t* a, const uint32_t* b) {
    asm volatile(
        "mma.sync.aligned.m16n8k16.row.col.f32.f16.f16.f32 "
        "{%0,%1,%2,%3}, {%4,%5,%6,%7}, {%8,%9}, {%0,%1,%2,%3};"
        : "+f"(c[0]), "+f"(c[1]), "+f"(c[2]), "+f"(c[3])
        : "r"(a[0]), "r"(a[1]), "r"(a[2]), "r"(a[3]), "r"(b[0]), "r"(b[1]));
}
__device__ __forceinline__ void ldsm4(uint32_t& r0, uint32_t& r1, uint32_t& r2, uint32_t& r3,
                                      uint32_t addr) {
    asm volatile("ldmatrix.sync.aligned.m8n8.x4.shared.b16 {%0,%1,%2,%3}, [%4];"
                 : "=r"(r0), "=r"(r1), "=r"(r2), "=r"(r3) : "r"(addr));
}

// ===========================================================================
// fp16 mma.sync GEMM — R8/R11 core (proven fastest; do not touch pipeline).
// SPLITK: gridDim.z=2; z splits this row-block's K range at the 128-aligned
//         midpoint of its (triangular) extent; z=1 writes Cv + NT*DM floats.
// ===========================================================================
template <bool CAUSAL, bool TRIK, bool RELU, bool BIAS, bool HALF_OUT, bool SPLITK>
__global__ __launch_bounds__(256, 2)
void hgemm2(const __half* __restrict__ A, const __half* __restrict__ Bt,
            const float* __restrict__ bias, void* __restrict__ Cv,
            int N, int Kdim, int lda, int ldb, float alpha)
{
    __shared__ __align__(16) uint32_t As[2][2048];
    __shared__ __align__(16) uint32_t Bs[2][2048];

    const int bx = blockIdx.x, by = blockIdx.y;
    if (CAUSAL && bx > by) return;

    const int tid  = threadIdx.x;
    const int wid  = tid >> 5;
    const int lane = tid & 31;
    const int g    = lane >> 2;
    const int tig  = lane & 3;
    const int l7   = lane & 7;
    const int q    = lane >> 3;

    const int wmt = (wid & 1) * 4;
    const int wnt = (wid >> 1) * 4;

    int kEnd = Kdim;
    if (TRIK) { int lim = (by + 1) * 128; kEnd = lim < Kdim ? lim : Kdim; }
    int kBeg = 0;
    if (SPLITK) {
        const int kH = ((by + 1) >> 1) << 7;   // 128-aligned midpoint of extent
        if (blockIdx.z == 0) kEnd = kH;
        else                 kBeg = kH;
    }
    const int niter = (kEnd - kBeg) >> 5;

    const int r0c = tid >> 2, c0c = tid & 3;
    const int w0 = r0c * 16 + ((c0c ^ ((r0c >> 1) & 3)) << 2);
    const int r1c = r0c + 64;
    const int w1 = r1c * 16 + ((c0c ^ ((r1c >> 1) & 3)) << 2);
    const __half* aG0 = A  + (size_t)(by * 128 + r0c) * (size_t)lda + kBeg + c0c * 8;
    const __half* aG1 = A  + (size_t)(by * 128 + r1c) * (size_t)lda + kBeg + c0c * 8;
    const __half* bG0 = Bt + (size_t)(bx * 128 + r0c) * (size_t)ldb + kBeg + c0c * 8;
    const __half* bG1 = Bt + (size_t)(bx * 128 + r1c) * (size_t)ldb + kBeg + c0c * 8;

    uint4 ra0, ra1, rb0, rb1;
#define LDG_T(k0) do { \
        ra0 = *(const uint4*)(aG0 + (k0)); \
        ra1 = *(const uint4*)(aG1 + (k0)); \
        rb0 = *(const uint4*)(bG0 + (k0)); \
        rb1 = *(const uint4*)(bG1 + (k0)); \
    } while (0)
#define STS_T(buf) do { \
        *(uint4*)&As[buf][w0] = ra0; \
        *(uint4*)&As[buf][w1] = ra1; \
        *(uint4*)&Bs[buf][w0] = rb0; \
        *(uint4*)&Bs[buf][w1] = rb1; \
    } while (0)

    const uint32_t aSm = smem_u32(As);
    const uint32_t bSm = smem_u32(Bs);

    uint32_t aOff[4][2], bOff[2][2];
#pragma unroll
    for (int m = 0; m < 4; m++) {
        int r = (wmt + m) * 16 + (q & 1) * 8 + l7;
#pragma unroll
        for (int ks = 0; ks < 2; ks++) {
            uint32_t c = (uint32_t)(2 * ks) + (uint32_t)(q >> 1);
            aOff[m][ks] = (uint32_t)r * 64u + ((c ^ ((uint32_t)(r >> 1) & 3u)) << 4);
        }
    }
#pragma unroll
    for (int p = 0; p < 2; p++) {
        int r = (wnt + 2 * p + (q >> 1)) * 8 + l7;
#pragma unroll
        for (int ks = 0; ks < 2; ks++) {
            uint32_t c = (uint32_t)(2 * ks) + (uint32_t)(q & 1);
            bOff[p][ks] = (uint32_t)r * 64u + ((c ^ ((uint32_t)(r >> 1) & 3u)) << 4);
        }
    }

    float acc[4][4][4];
#pragma unroll
    for (int i = 0; i < 4; i++)
#pragma unroll
        for (int j = 0; j < 4; j++)
#pragma unroll
            for (int t = 0; t < 4; t++) acc[i][j][t] = 0.f;

    if (niter > 0) {
        LDG_T(0);
        STS_T(0);
        __syncthreads();

        for (int i = 0; i < niter; i++) {
            const int b = i & 1;
            if (i + 1 < niter) LDG_T((i + 1) * 32);

            const uint32_t aBase = aSm + (uint32_t)b * 8192u;
            const uint32_t bBase = bSm + (uint32_t)b * 8192u;
#pragma unroll
            for (int ks = 0; ks < 2; ks++) {
                uint32_t af[4][4], bf[4][2];
#pragma unroll
                for (int m = 0; m < 4; m++)
                    ldsm4(af[m][0], af[m][1], af[m][2], af[m][3], aBase + aOff[m][ks]);
#pragma unroll
                for (int p = 0; p < 2; p++)
                    ldsm4(bf[2 * p][0], bf[2 * p][1], bf[2 * p + 1][0], bf[2 * p + 1][1],
                          bBase + bOff[p][ks]);
#pragma unroll
                for (int m = 0; m < 4; m++)
#pragma unroll
                    for (int n = 0; n < 4; n++)
                        mma_f16(acc[m][n], af[m], bf[n]);
            }

            if (i + 1 < niter) STS_T(b ^ 1);
            __syncthreads();
        }
    }

    // ---- epilogue ----
    const size_t outOff = (SPLITK && blockIdx.z == 1) ? (size_t)NT * DM : 0;
    const int rowBase = by * 128 + (wid & 1) * 64 + g;
    const int colBase = bx * 128 + (wid >> 1) * 32 + tig * 2;
#pragma unroll
    for (int m = 0; m < 4; m++) {
        const int r0 = rowBase + m * 16;
#pragma unroll
        for (int n = 0; n < 4; n++) {
            const int col = colBase + n * 8;
            float b0 = 0.f, b1 = 0.f;
            if (BIAS) { b0 = bias[col]; b1 = bias[col + 1]; }
            float v0x = acc[m][n][0] * alpha + b0;
            float v0y = acc[m][n][1] * alpha + b1;
            float v1x = acc[m][n][2] * alpha + b0;
            float v1y = acc[m][n][3] * alpha + b1;
            if (RELU) {
                v0x = fmaxf(v0x, 0.f); v0y = fmaxf(v0y, 0.f);
                v1x = fmaxf(v1x, 0.f); v1y = fmaxf(v1y, 0.f);
            }
            if (HALF_OUT) {
                __half* C = (__half*)Cv;
                *(__half2*)(C + (size_t)r0 * N + col)       = __floats2half2_rn(v0x, v0y);
                *(__half2*)(C + (size_t)(r0 + 8) * N + col) = __floats2half2_rn(v1x, v1y);
            } else {
                float* C = (float*)Cv + outOff;
                *(float2*)(C + (size_t)r0 * N + col)       = make_float2(v0x, v0y);
                *(float2*)(C + (size_t)(r0 + 8) * N + col) = make_float2(v1x, v1y);
            }
        }
    }
#undef LDG_T
#undef STS_T
}

// ===========================================================================
// Merged prologue: f2h(E), weight transposes, bias concat (one launch).
// ===========================================================================
__device__ __forceinline__ void tile_transpose_f2h(
    const float* __restrict__ in, __half* __restrict__ out,
    int inS, int outS, int bcx, int bry, int tid)
{
    __shared__ float t[32][33];
    const int x = tid & 31, y = tid >> 5;
    const int bc = bcx * 32, br = bry * 32;
#pragma unroll
    for (int j = 0; j < 32; j += 8)
        t[y + j][x] = in[(size_t)(br + y + j) * inS + bc + x];
    __syncthreads();
#pragma unroll
    for (int j = 0; j < 32; j += 8)
        out[(size_t)(bc + y + j) * outS + br + x] = __float2half(t[x][y + j]);
}

__global__ __launch_bounds__(256)
void prep(const float* __restrict__ E,
          const float* __restrict__ Wq, const float* __restrict__ Wk,
          const float* __restrict__ Wv,
          const float* __restrict__ W1, const float* __restrict__ W2,
          const float* __restrict__ bq, const float* __restrict__ bk,
          const float* __restrict__ bv,
          __half* __restrict__ Eh, __half* __restrict__ Wqkvth,
          __half* __restrict__ W1th, __half* __restrict__ W2th,
          float* __restrict__ bqkv)
{
    const int bid = blockIdx.x;
    const int tid = threadIdx.x;

    if (bid < 4096) {
        int i = bid * 256 + tid;
        float4 v = ((const float4*)E)[i];
        ((__half2*)Eh)[i * 2]     = __floats2half2_rn(v.x, v.y);
        ((__half2*)Eh)[i * 2 + 1] = __floats2half2_rn(v.z, v.w);
    } else if (bid < 7168) {
        int t = bid - 4096;
        int which = t >> 10;
        int tt = t & 1023;
        const float* src = (which == 0) ? Wq : (which == 1) ? Wk : Wv;
        __half* dst = Wqkvth + (size_t)which * 1024 * DM;
        tile_transpose_f2h(src, dst, DM, DM, tt & 31, tt >> 5, tid);
    } else if (bid < 11264) {
        int t = bid - 7168;
        tile_transpose_f2h(W1, W1th, DF, DM, t & 127, t >> 7, tid);
    } else if (bid < 15360) {
        int t = bid - 11264;
        tile_transpose_f2h(W2, W2th, DM, DF, t & 31, t >> 5, tid);
    } else {
        int i = (bid - 15360) * 256 + tid;
        float v = (i < 1024) ? bq[i] : (i < 2048) ? bk[i - 1024] : bv[i - 2048];
        bqkv[i] = v;
    }
}

// ============ transpose fp16 -> fp16 (Vth) ============
__global__ void transpose_h2h(const __half* __restrict__ in, __half* __restrict__ out,
                              int inS, int outS)
{
    __shared__ __half t[32][34];
    const int bc = blockIdx.x * 32;
    const int br = blockIdx.y * 32;
    const int x = threadIdx.x, y = threadIdx.y;
#pragma unroll
    for (int j = 0; j < 32; j += 8)
        t[y + j][x] = in[(size_t)(br + y + j) * inS + bc + x];
    __syncthreads();
#pragma unroll
    for (int j = 0; j < 32; j += 8)
        out[(size_t)(bc + y + j) * outS + br + x] = t[x][y + j];
}

// ============ fast exp (FMA pipe) ============
__device__ __forceinline__ float fast_exp(float x) {
    float y = x * 1.4426950408889634f;
    float n = rintf(y);
    float f = y - n;
    float p = 1.5403530393e-4f;
    p = fmaf(p, f, 1.3333558146e-3f);
    p = fmaf(p, f, 9.6181291076e-3f);
    p = fmaf(p, f, 5.5504108665e-2f);
    p = fmaf(p, f, 2.4022650696e-1f);
    p = fmaf(p, f, 6.9314718056e-1f);
    p = fmaf(p, f, 1.0f);
    float ec = fmaxf(n, -126.f);
    return __int_as_float(((int)ec + 127) << 23) * p;
}

// ============ causal softmax (register-resident, R14) ============
__global__ void softmax_causal(const float* __restrict__ S, __half* __restrict__ Sh)
{
    const int r = blockIdx.x;
    const int tid = threadIdx.x;
    const int limit = ((r >> 7) + 1) << 7;
    const int nc = (limit + 1023) >> 10;
    const float* row = S + (size_t)r * NT;
    __half* rowh = Sh + (size_t)r * NT;

    float4 v[4];
    float m = -1e30f;
#pragma unroll
    for (int i = 0; i < 4; i++) {
        if (i < nc) {
            const int j = i * 1024 + tid * 4;
            float4 t = *(const float4*)(row + j);
            t.x = (j     <= r) ? t.x : -1e30f;
            t.y = (j + 1 <= r) ? t.y : -1e30f;
            t.z = (j + 2 <= r) ? t.z : -1e30f;
            t.w = (j + 3 <= r) ? t.w : -1e30f;
            v[i] = t;
            m = fmaxf(m, fmaxf(fmaxf(t.x, t.y), fmaxf(t.z, t.w)));
        }
    }

    __shared__ float redm[8], reds[8];
#pragma unroll
    for (int o = 16; o > 0; o >>= 1) m = fmaxf(m, __shfl_xor_sync(0xffffffffu, m, o));
    if ((tid & 31) == 0) redm[tid >> 5] = m;
    __syncthreads();
    m = redm[0];
#pragma unroll
    for (int i = 1; i < 8; i++) m = fmaxf(m, redm[i]);

    float s = 0.f;
#pragma unroll
    for (int i = 0; i < 4; i++) {
        if (i < nc) {
            v[i].x = fast_exp(v[i].x - m);
            v[i].y = fast_exp(v[i].y - m);
            v[i].z = fast_exp(v[i].z - m);
            v[i].w = fast_exp(v[i].w - m);
            s += (v[i].x + v[i].y) + (v[i].z + v[i].w);
        }
    }
#pragma unroll
    for (int o = 16; o > 0; o >>= 1) s += __shfl_xor_sync(0xffffffffu, s, o);
    if ((tid & 31) == 0) reds[tid >> 5] = s;
    __syncthreads();
    s = reds[0];
#pragma unroll
    for (int i = 1; i < 8; i++) s += reds[i];

    const float inv = 1.f / s;
#pragma unroll
    for (int i = 0; i < 4; i++) {
        if (i < nc) {
            const int j = i * 1024 + tid * 4;
            *(__half2*)(rowh + j)     = __floats2half2_rn(v[i].x * inv, v[i].y * inv);
            *(__half2*)(rowh + j + 2) = __floats2half2_rn(v[i].z * inv, v[i].w * inv);
        }
    }
}

// ============ add + LayerNorm (AE0 + AE1 + E) -> fp16 X ============
__global__ void add_layernorm(const float* __restrict__ AE0, const float* __restrict__ AE1,
                              const float* __restrict__ E,
                              const float* __restrict__ gamma, const float* __restrict__ beta,
                              __half* __restrict__ X)
{
    const int r = blockIdx.x;
    const int tid = threadIdx.x;
    float4 a0 = ((const float4*)(AE0 + (size_t)r * DM))[tid];
    float4 a1 = ((const float4*)(AE1 + (size_t)r * DM))[tid];
    float4 e  = ((const float4*)(E   + (size_t)r * DM))[tid];
    float x0 = a0.x + a1.x + e.x, x1 = a0.y + a1.y + e.y;
    float x2 = a0.z + a1.z + e.z, x3 = a0.w + a1.w + e.w;
    float s = x0 + x1 + x2 + x3;
    float q = x0 * x0 + x1 * x1 + x2 * x2 + x3 * x3;
    __shared__ float rs[8], rq[8];
#pragma unroll
    for (int o = 16; o > 0; o >>= 1) {
        s += __shfl_xor_sync(0xffffffffu, s, o);
        q += __shfl_xor_sync(0xffffffffu, q, o);
    }
    if ((tid & 31) == 0) { rs[tid >> 5] = s; rq[tid >> 5] = q; }
    __syncthreads();
    s = rs[0]; q = rq[0];
#pragma unroll
    for (int i = 1; i < 8; i++) { s += rs[i]; q += rq[i]; }
    const float mean = s * (1.f / DM);
    const float var  = q * (1.f / DM) - mean * mean;
    const float inv  = rsqrtf(var + 1e-5f);
    float4 gg = ((const float4*)gamma)[tid];
    float4 bb = ((const float4*)beta)[tid];
    __half2 o0 = __floats2half2_rn((x0 - mean) * inv * gg.x + bb.x,
                                   (x1 - mean) * inv * gg.y + bb.y);
    __half2 o1 = __floats2half2_rn((x2 - mean) * inv * gg.z + bb.z,
                                   (x3 - mean) * inv * gg.w + bb.w);
    ((__half2*)(X + (size_t)r * DM))[tid * 2]     = o0;
    ((__half2*)(X + (size_t)r * DM))[tid * 2 + 1] = o1;
}

// ============ launch ============
extern "C" void kernel_launch(void* const* d_in, const int* in_sizes, int n_in,
                              void* d_out, int out_size)
{
    (void)in_sizes; (void)n_in; (void)out_size;
    const float* E     = (const float*)d_in[0];
    const float* Wq    = (const float*)d_in[1];
    const float* bq    = (const float*)d_in[2];
    const float* Wk    = (const float*)d_in[3];
    const float* bk    = (const float*)d_in[4];
    const float* Wv    = (const float*)d_in[5];
    const float* bv    = (const float*)d_in[6];
    const float* gamma = (const float*)d_in[7];
    const float* beta  = (const float*)d_in[8];
    const float* W1    = (const float*)d_in[9];
    const float* b1    = (const float*)d_in[10];
    const float* W2    = (const float*)d_in[11];
    const float* b2    = (const float*)d_in[12];
    float* out = (float*)d_out;

    __half *Eh, *QKVh, *Sh, *Xh, *Hh, *Wqkvth, *W1th, *W2th, *Vth;
    float *S, *AE, *AE2, *bqkv;
    cudaGetSymbolAddress((void**)&Eh,     g_Eh);
    cudaGetSymbolAddress((void**)&QKVh,   g_QKVh);
    cudaGetSymbolAddress((void**)&S,      g_S);
    cudaGetSymbolAddress((void**)&Sh,     g_Sh);
    cudaGetSymbolAddress((void**)&AE,     g_AE);
    cudaGetSymbolAddress((void**)&AE2,    g_AE2);
    cudaGetSymbolAddress((void**)&Xh,     g_Xh);
    cudaGetSymbolAddress((void**)&Hh,     g_Hh);
    cudaGetSymbolAddress((void**)&Wqkvth, g_Wqkvth);
    cudaGetSymbolAddress((void**)&W1th,   g_W1th);
    cudaGetSymbolAddress((void**)&W2th,   g_W2th);
    cudaGetSymbolAddress((void**)&Vth,    g_Vth);
    cudaGetSymbolAddress((void**)&bqkv,   g_bqkv);

    // ONE merged prologue launch
    prep<<<15372, 256>>>(E, Wq, Wk, Wv, W1, W2, bq, bk, bv,
                         Eh, Wqkvth, W1th, W2th, bqkv);

    dim3 blk(256);
    dim3 tb(32, 8);

    // fused QKV projection -> half [4096, 3072]
    hgemm2<false, false, false, true, true, false><<<dim3(3072 / 128, NT / 128), blk>>>(
        Eh, Wqkvth, bqkv, QKVh, 3072, DM, DM, DM, 1.f);

    // Vth[d][t] = V[t][d]
    transpose_h2h<<<dim3(DM / 32, NT / 32), tb>>>(QKVh + 2048, Vth, 3072, NT);

    // S = Q @ K^T / 32 (causal lower blocks) -> fp32
    hgemm2<true, false, false, false, false, false><<<dim3(NT / 128, NT / 128), blk>>>(
        QKVh, QKVh + 1024, nullptr, S, NT, DM, 3072, 3072, 0.03125f);

    softmax_causal<<<NT, 256>>>(S, Sh);

    // AE = probs @ V, split-K=2 balanced on the triangle; partials to AE/AE2
    // (AE2 = AE + NT*DM inside the kernel via outOff; pass AE as base)
    hgemm2<false, true, false, false, false, true><<<dim3(DM / 128, NT / 128, 2), blk>>>(
        Sh, Vth, nullptr, AE, DM, NT, NT, NT, 1.f);

    add_layernorm<<<NT, 256>>>(AE, AE + (size_t)NT * DM, E, gamma, beta, Xh);

    // FFN
    hgemm2<false, false, true, true, true, false><<<dim3(DF / 128, NT / 128), blk>>>(
        Xh, W1th, b1, Hh, DF, DM, DM, DM, 1.f);
    hgemm2<false, false, false, true, false, false><<<dim3(DM / 128, NT / 128), blk>>>(
        Hh, W2th, b2, out, DM, DF, DF, DF, 1.f);
}

// round 17
// speedup vs baseline: 1.5228x; 1.0059x over previous
#include <cuda_runtime.h>
#include <cuda_fp16.h>
#include <cstdint>

#define NT 4096   // tokens
#define DM 1024   // model dim
#define DF 4096   // ffn dim

// ---- scratch (static device globals; allowed) ----
__device__ __half g_Eh[(size_t)NT * DM];
__device__ __half g_QKVh[(size_t)NT * 3072];      // fused Q|K|V (half), stride 3072
__device__ float  g_S[(size_t)NT * NT];           // attention scores fp32
__device__ __half g_Sh[(size_t)NT * NT];          // softmax probs half
__device__ float  g_AEd[(size_t)2 * NT * DM];     // AV partials z0|z1 (contiguous)
__device__ __half g_Xh[NT * DM];
__device__ __half g_Hh[(size_t)NT * DF];
__device__ __half g_Wqkvth[3072 * DM];            // [3072][1024] W^T half
__device__ __half g_W1th[(size_t)DF * DM];        // [4096][1024]
__device__ __half g_W2th[(size_t)DM * DF];        // [1024][4096]
__device__ __half g_Vth[(size_t)DM * NT];         // [1024][4096] V^T half
__device__ float  g_bqkv[3072];

__device__ __forceinline__ uint32_t smem_u32(const void* p) {
    uint32_t a;
    asm("{ .reg .u64 t; cvta.to.shared.u64 t, %1; cvt.u32.u64 %0, t; }" : "=r"(a) : "l"(p));
    return a;
}
__device__ __forceinline__ void mma_f16(float* c, const uint32_t* a, const uint32_t* b) {
    asm volatile(
        "mma.sync.aligned.m16n8k16.row.col.f32.f16.f16.f32 "
        "{%0,%1,%2,%3}, {%4,%5,%6,%7}, {%8,%9}, {%0,%1,%2,%3};"
        : "+f"(c[0]), "+f"(c[1]), "+f"(c[2]), "+f"(c[3])
        : "r"(a[0]), "r"(a[1]), "r"(a[2]), "r"(a[3]), "r"(b[0]), "r"(b[1]));
}
__device__ __forceinline__ void ldsm4(uint32_t& r0, uint32_t& r1, uint32_t& r2, uint32_t& r3,
                                      uint32_t addr) {
    asm volatile("ldmatrix.sync.aligned.m8n8.x4.shared.b16 {%0,%1,%2,%3}, [%4];"
                 : "=r"(r0), "=r"(r1), "=r"(r2), "=r"(r3) : "r"(addr));
}

// ===========================================================================
// fp16 mma.sync GEMM — R8/R11 core (legacy-HMMA ceiling; pipeline untouched).
// SPLITK: gridDim.z=2 splits each row-block's triangular K extent at its
//         128-aligned midpoint; z=1 writes Cv + NT*DM floats.
// AUX (block-range fusion, gridDim.z=2, z==1 blocks do side work and exit):
//   AUX=1: Vth transpose, 4 tiles/block   (fused into S-GEMM launch)
//   AUX=2: W1/W2 transpose f2h, 11 tiles/block (fused into QKV launch)
// ===========================================================================
template <int AUX, bool CAUSAL, bool TRIK, bool RELU, bool BIAS, bool HALF_OUT, bool SPLITK>
__global__ __launch_bounds__(256, 2)
void hgemm2(const __half* __restrict__ A, const __half* __restrict__ Bt,
            const float* __restrict__ bias, void* __restrict__ Cv,
            int N, int Kdim, int lda, int ldb, float alpha,
            const void* ax0, const void* ax1, void* ay0, void* ay1)
{
    const int tid = threadIdx.x;

    if constexpr (AUX == 1) {
        if (blockIdx.z == 1) {            // Vth[d][t] = QKV[t][2048+d]
            __shared__ __half th[32][34];
            const __half* in = (const __half*)ax0;   // QKVh + 2048, stride 3072
            __half* outp = (__half*)ay0;             // Vth, stride NT
            const int x = tid & 31, y = tid >> 5;
            const int base = (blockIdx.y * gridDim.x + blockIdx.x) * 4;
#pragma unroll
            for (int j = 0; j < 4; j++) {
                const int id = base + j;             // < 4096
                const int bc = (id & 31) * 32;       // d-dim
                const int br = (id >> 5) * 32;       // t-dim
#pragma unroll
                for (int jj = 0; jj < 32; jj += 8)
                    th[y + jj][x] = in[(size_t)(br + y + jj) * 3072 + bc + x];
                __syncthreads();
#pragma unroll
                for (int jj = 0; jj < 32; jj += 8)
                    outp[(size_t)(bc + y + jj) * NT + br + x] = th[x][y + jj];
                __syncthreads();
            }
            return;
        }
    }
    if constexpr (AUX == 2) {
        if (blockIdx.z == 1) {            // W1/W2 transposed f2h (8192 tiles)
            __shared__ float tf[32][33];
            const float* W1 = (const float*)ax0;     // [1024][4096]
            const float* W2 = (const float*)ax1;     // [4096][1024]
            __half* W1th = (__half*)ay0;             // [4096][1024]
            __half* W2th = (__half*)ay1;             // [1024][4096]
            const int x = tid & 31, y = tid >> 5;
            const int base = (blockIdx.y * gridDim.x + blockIdx.x) * 11;
            for (int j = 0; j < 11; j++) {
                const int id = base + j;
                if (id >= 8192) break;
                const float* src; __half* dst; int inS, outS, bc, br;
                if (id < 4096) {                     // W1 tiles: grid 128 x 32
                    src = W1; dst = W1th; inS = DF; outS = DM;
                    bc = (id & 127) * 32; br = (id >> 7) * 32;
                } else {                             // W2 tiles: grid 32 x 128
                    const int t = id - 4096;
                    src = W2; dst = W2th; inS = DM; outS = DF;
                    bc = (t & 31) * 32; br = (t >> 5) * 32;
                }
#pragma unroll
                for (int jj = 0; jj < 32; jj += 8)
                    tf[y + jj][x] = src[(size_t)(br + y + jj) * inS + bc + x];
                __syncthreads();
#pragma unroll
                for (int jj = 0; jj < 32; jj += 8)
                    dst[(size_t)(bc + y + jj) * outS + br + x] = __float2half(tf[x][y + jj]);
                __syncthreads();
            }
            return;
        }
    }

    __shared__ __align__(16) uint32_t As[2][2048];
    __shared__ __align__(16) uint32_t Bs[2][2048];

    const int bx = blockIdx.x, by = blockIdx.y;
    if (CAUSAL && bx > by) return;

    const int wid  = tid >> 5;
    const int lane = tid & 31;
    const int g    = lane >> 2;
    const int tig  = lane & 3;
    const int l7   = lane & 7;
    const int q    = lane >> 3;

    const int wmt = (wid & 1) * 4;
    const int wnt = (wid >> 1) * 4;

    int kEnd = Kdim;
    if (TRIK) { int lim = (by + 1) * 128; kEnd = lim < Kdim ? lim : Kdim; }
    int kBeg = 0;
    if (SPLITK) {
        const int kH = ((by + 1) >> 1) << 7;
        if (blockIdx.z == 0) kEnd = kH;
        else                 kBeg = kH;
    }
    const int niter = (kEnd - kBeg) >> 5;

    const int r0c = tid >> 2, c0c = tid & 3;
    const int w0 = r0c * 16 + ((c0c ^ ((r0c >> 1) & 3)) << 2);
    const int r1c = r0c + 64;
    const int w1 = r1c * 16 + ((c0c ^ ((r1c >> 1) & 3)) << 2);
    const __half* aG0 = A  + (size_t)(by * 128 + r0c) * (size_t)lda + kBeg + c0c * 8;
    const __half* aG1 = A  + (size_t)(by * 128 + r1c) * (size_t)lda + kBeg + c0c * 8;
    const __half* bG0 = Bt + (size_t)(bx * 128 + r0c) * (size_t)ldb + kBeg + c0c * 8;
    const __half* bG1 = Bt + (size_t)(bx * 128 + r1c) * (size_t)ldb + kBeg + c0c * 8;

    uint4 ra0, ra1, rb0, rb1;
#define LDG_T(k0) do { \
        ra0 = *(const uint4*)(aG0 + (k0)); \
        ra1 = *(const uint4*)(aG1 + (k0)); \
        rb0 = *(const uint4*)(bG0 + (k0)); \
        rb1 = *(const uint4*)(bG1 + (k0)); \
    } while (0)
#define STS_T(buf) do { \
        *(uint4*)&As[buf][w0] = ra0; \
        *(uint4*)&As[buf][w1] = ra1; \
        *(uint4*)&Bs[buf][w0] = rb0; \
        *(uint4*)&Bs[buf][w1] = rb1; \
    } while (0)

    const uint32_t aSm = smem_u32(As);
    const uint32_t bSm = smem_u32(Bs);

    uint32_t aOff[4][2], bOff[2][2];
#pragma unroll
    for (int m = 0; m < 4; m++) {
        int r = (wmt + m) * 16 + (q & 1) * 8 + l7;
#pragma unroll
        for (int ks = 0; ks < 2; ks++) {
            uint32_t c = (uint32_t)(2 * ks) + (uint32_t)(q >> 1);
            aOff[m][ks] = (uint32_t)r * 64u + ((c ^ ((uint32_t)(r >> 1) & 3u)) << 4);
        }
    }
#pragma unroll
    for (int p = 0; p < 2; p++) {
        int r = (wnt + 2 * p + (q >> 1)) * 8 + l7;
#pragma unroll
        for (int ks = 0; ks < 2; ks++) {
            uint32_t c = (uint32_t)(2 * ks) + (uint32_t)(q & 1);
            bOff[p][ks] = (uint32_t)r * 64u + ((c ^ ((uint32_t)(r >> 1) & 3u)) << 4);
        }
    }

    float acc[4][4][4];
#pragma unroll
    for (int i = 0; i < 4; i++)
#pragma unroll
        for (int j = 0; j < 4; j++)
#pragma unroll
            for (int t = 0; t < 4; t++) acc[i][j][t] = 0.f;

    if (niter > 0) {
        LDG_T(0);
        STS_T(0);
        __syncthreads();

        for (int i = 0; i < niter; i++) {
            const int b = i & 1;
            if (i + 1 < niter) LDG_T((i + 1) * 32);

            const uint32_t aBase = aSm + (uint32_t)b * 8192u;
            const uint32_t bBase = bSm + (uint32_t)b * 8192u;
#pragma unroll
            for (int ks = 0; ks < 2; ks++) {
                uint32_t af[4][4], bf[4][2];
#pragma unroll
                for (int m = 0; m < 4; m++)
                    ldsm4(af[m][0], af[m][1], af[m][2], af[m][3], aBase + aOff[m][ks]);
#pragma unroll
                for (int p = 0; p < 2; p++)
                    ldsm4(bf[2 * p][0], bf[2 * p][1], bf[2 * p + 1][0], bf[2 * p + 1][1],
                          bBase + bOff[p][ks]);
#pragma unroll
                for (int m = 0; m < 4; m++)
#pragma unroll
                    for (int n = 0; n < 4; n++)
                        mma_f16(acc[m][n], af[m], bf[n]);
            }

            if (i + 1 < niter) STS_T(b ^ 1);
            __syncthreads();
        }
    }

    // ---- epilogue ----
    const size_t outOff = (SPLITK && blockIdx.z == 1) ? (size_t)NT * DM : 0;
    const int rowBase = by * 128 + (wid & 1) * 64 + g;
    const int colBase = bx * 128 + (wid >> 1) * 32 + tig * 2;
#pragma unroll
    for (int m = 0; m < 4; m++) {
        const int r0 = rowBase + m * 16;
#pragma unroll
        for (int n = 0; n < 4; n++) {
            const int col = colBase + n * 8;
            float b0 = 0.f, b1 = 0.f;
            if (BIAS) { b0 = bias[col]; b1 = bias[col + 1]; }
            float v0x = acc[m][n][0] * alpha + b0;
            float v0y = acc[m][n][1] * alpha + b1;
            float v1x = acc[m][n][2] * alpha + b0;
            float v1y = acc[m][n][3] * alpha + b1;
            if (RELU) {
                v0x = fmaxf(v0x, 0.f); v0y = fmaxf(v0y, 0.f);
                v1x = fmaxf(v1x, 0.f); v1y = fmaxf(v1y, 0.f);
            }
            if (HALF_OUT) {
                __half* C = (__half*)Cv;
                *(__half2*)(C + (size_t)r0 * N + col)       = __floats2half2_rn(v0x, v0y);
                *(__half2*)(C + (size_t)(r0 + 8) * N + col) = __floats2half2_rn(v1x, v1y);
            } else {
                float* C = (float*)Cv + outOff;
                *(float2*)(C + (size_t)r0 * N + col)       = make_float2(v0x, v0y);
                *(float2*)(C + (size_t)(r0 + 8) * N + col) = make_float2(v1x, v1y);
            }
        }
    }
#undef LDG_T
#undef STS_T
}

// ===========================================================================
// prep1: f2h(E) + Wq/Wk/Wv transposes + bias concat (deps of QKV GEMM only).
// ===========================================================================
__global__ __launch_bounds__(256)
void prep1(const float* __restrict__ E,
           const float* __restrict__ Wq, const float* __restrict__ Wk,
           const float* __restrict__ Wv,
           const float* __restrict__ bq, const float* __restrict__ bk,
           const float* __restrict__ bv,
           __half* __restrict__ Eh, __half* __restrict__ Wqkvth,
           float* __restrict__ bqkv)
{
    const int bid = blockIdx.x;
    const int tid = threadIdx.x;

    if (bid < 4096) {
        int i = bid * 256 + tid;
        float4 v = ((const float4*)E)[i];
        ((__half2*)Eh)[i * 2]     = __floats2half2_rn(v.x, v.y);
        ((__half2*)Eh)[i * 2 + 1] = __floats2half2_rn(v.z, v.w);
    } else if (bid < 7168) {
        __shared__ float t[32][33];
        int tt = (bid - 4096) & 1023;
        int which = (bid - 4096) >> 10;
        const float* src = (which == 0) ? Wq : (which == 1) ? Wk : Wv;
        __half* dst = Wqkvth + (size_t)which * 1024 * DM;
        const int x = tid & 31, y = tid >> 5;
        const int bc = (tt & 31) * 32, br = (tt >> 5) * 32;
#pragma unroll
        for (int j = 0; j < 32; j += 8)
            t[y + j][x] = src[(size_t)(br + y + j) * DM + bc + x];
        __syncthreads();
#pragma unroll
        for (int j = 0; j < 32; j += 8)
            dst[(size_t)(bc + y + j) * DM + br + x] = __float2half(t[x][y + j]);
    } else {
        int i = (bid - 7168) * 256 + tid;
        if (i < 3072) {
            float v = (i < 1024) ? bq[i] : (i < 2048) ? bk[i - 1024] : bv[i - 2048];
            bqkv[i] = v;
        }
    }
}

// ============ fast exp (FMA pipe) ============
__device__ __forceinline__ float fast_exp(float x) {
    float y = x * 1.4426950408889634f;
    float n = rintf(y);
    float f = y - n;
    float p = 1.5403530393e-4f;
    p = fmaf(p, f, 1.3333558146e-3f);
    p = fmaf(p, f, 9.6181291076e-3f);
    p = fmaf(p, f, 5.5504108665e-2f);
    p = fmaf(p, f, 2.4022650696e-1f);
    p = fmaf(p, f, 6.9314718056e-1f);
    p = fmaf(p, f, 1.0f);
    float ec = fmaxf(n, -126.f);
    return __int_as_float(((int)ec + 127) << 23) * p;
}

// ============ causal softmax (register-resident) ============
__global__ void softmax_causal(const float* __restrict__ S, __half* __restrict__ Sh)
{
    const int r = blockIdx.x;
    const int tid = threadIdx.x;
    const int limit = ((r >> 7) + 1) << 7;
    const int nc = (limit + 1023) >> 10;
    const float* row = S + (size_t)r * NT;
    __half* rowh = Sh + (size_t)r * NT;

    float4 v[4];
    float m = -1e30f;
#pragma unroll
    for (int i = 0; i < 4; i++) {
        if (i < nc) {
            const int j = i * 1024 + tid * 4;
            float4 t = *(const float4*)(row + j);
            t.x = (j     <= r) ? t.x : -1e30f;
            t.y = (j + 1 <= r) ? t.y : -1e30f;
            t.z = (j + 2 <= r) ? t.z : -1e30f;
            t.w = (j + 3 <= r) ? t.w : -1e30f;
            v[i] = t;
            m = fmaxf(m, fmaxf(fmaxf(t.x, t.y), fmaxf(t.z, t.w)));
        }
    }

    __shared__ float redm[8], reds[8];
#pragma unroll
    for (int o = 16; o > 0; o >>= 1) m = fmaxf(m, __shfl_xor_sync(0xffffffffu, m, o));
    if ((tid & 31) == 0) redm[tid >> 5] = m;
    __syncthreads();
    m = redm[0];
#pragma unroll
    for (int i = 1; i < 8; i++) m = fmaxf(m, redm[i]);

    float s = 0.f;
#pragma unroll
    for (int i = 0; i < 4; i++) {
        if (i < nc) {
            v[i].x = fast_exp(v[i].x - m);
            v[i].y = fast_exp(v[i].y - m);
            v[i].z = fast_exp(v[i].z - m);
            v[i].w = fast_exp(v[i].w - m);
            s += (v[i].x + v[i].y) + (v[i].z + v[i].w);
        }
    }
#pragma unroll
    for (int o = 16; o > 0; o >>= 1) s += __shfl_xor_sync(0xffffffffu, s, o);
    if ((tid & 31) == 0) reds[tid >> 5] = s;
    __syncthreads();
    s = reds[0];
#pragma unroll
    for (int i = 1; i < 8; i++) s += reds[i];

    const float inv = 1.f / s;
#pragma unroll
    for (int i = 0; i < 4; i++) {
        if (i < nc) {
            const int j = i * 1024 + tid * 4;
            *(__half2*)(rowh + j)     = __floats2half2_rn(v[i].x * inv, v[i].y * inv);
            *(__half2*)(rowh + j + 2) = __floats2half2_rn(v[i].z * inv, v[i].w * inv);
        }
    }
}

// ============ add + LayerNorm (AE0 + AE1 + E) -> fp16 X ============
__global__ void add_layernorm(const float* __restrict__ AE0, const float* __restrict__ AE1,
                              const float* __restrict__ E,
                              const float* __restrict__ gamma, const float* __restrict__ beta,
                              __half* __restrict__ X)
{
    const int r = blockIdx.x;
    const int tid = threadIdx.x;
    float4 a0 = ((const float4*)(AE0 + (size_t)r * DM))[tid];
    float4 a1 = ((const float4*)(AE1 + (size_t)r * DM))[tid];
    float4 e  = ((const float4*)(E   + (size_t)r * DM))[tid];
    float x0 = a0.x + a1.x + e.x, x1 = a0.y + a1.y + e.y;
    float x2 = a0.z + a1.z + e.z, x3 = a0.w + a1.w + e.w;
    float s = x0 + x1 + x2 + x3;
    float q = x0 * x0 + x1 * x1 + x2 * x2 + x3 * x3;
    __shared__ float rs[8], rq[8];
#pragma unroll
    for (int o = 16; o > 0; o >>= 1) {
        s += __shfl_xor_sync(0xffffffffu, s, o);
        q += __shfl_xor_sync(0xffffffffu, q, o);
    }
    if ((tid & 31) == 0) { rs[tid >> 5] = s; rq[tid >> 5] = q; }
    __syncthreads();
    s = rs[0]; q = rq[0];
#pragma unroll
    for (int i = 1; i < 8; i++) { s += rs[i]; q += rq[i]; }
    const float mean = s * (1.f / DM);
    const float var  = q * (1.f / DM) - mean * mean;
    const float inv  = rsqrtf(var + 1e-5f);
    float4 gg = ((const float4*)gamma)[tid];
    float4 bb = ((const float4*)beta)[tid];
    __half2 o0 = __floats2half2_rn((x0 - mean) * inv * gg.x + bb.x,
                                   (x1 - mean) * inv * gg.y + bb.y);
    __half2 o1 = __floats2half2_rn((x2 - mean) * inv * gg.z + bb.z,
                                   (x3 - mean) * inv * gg.w + bb.w);
    ((__half2*)(X + (size_t)r * DM))[tid * 2]     = o0;
    ((__half2*)(X + (size_t)r * DM))[tid * 2 + 1] = o1;
}

// ============ launch ============
extern "C" void kernel_launch(void* const* d_in, const int* in_sizes, int n_in,
                              void* d_out, int out_size)
{
    (void)in_sizes; (void)n_in; (void)out_size;
    const float* E     = (const float*)d_in[0];
    const float* Wq    = (const float*)d_in[1];
    const float* bq    = (const float*)d_in[2];
    const float* Wk    = (const float*)d_in[3];
    const float* bk    = (const float*)d_in[4];
    const float* Wv    = (const float*)d_in[5];
    const float* bv    = (const float*)d_in[6];
    const float* gamma = (const float*)d_in[7];
    const float* beta  = (const float*)d_in[8];
    const float* W1    = (const float*)d_in[9];
    const float* b1    = (const float*)d_in[10];
    const float* W2    = (const float*)d_in[11];
    const float* b2    = (const float*)d_in[12];
    float* out = (float*)d_out;

    __half *Eh, *QKVh, *Sh, *Xh, *Hh, *Wqkvth, *W1th, *W2th, *Vth;
    float *S, *AEd, *bqkv;
    cudaGetSymbolAddress((void**)&Eh,     g_Eh);
    cudaGetSymbolAddress((void**)&QKVh,   g_QKVh);
    cudaGetSymbolAddress((void**)&S,      g_S);
    cudaGetSymbolAddress((void**)&Sh,     g_Sh);
    cudaGetSymbolAddress((void**)&AEd,    g_AEd);
    cudaGetSymbolAddress((void**)&Xh,     g_Xh);
    cudaGetSymbolAddress((void**)&Hh,     g_Hh);
    cudaGetSymbolAddress((void**)&Wqkvth, g_Wqkvth);
    cudaGetSymbolAddress((void**)&W1th,   g_W1th);
    cudaGetSymbolAddress((void**)&W2th,   g_W2th);
    cudaGetSymbolAddress((void**)&Vth,    g_Vth);
    cudaGetSymbolAddress((void**)&bqkv,   g_bqkv);

    dim3 blk(256);

    // prologue: E/Wqkv/bias only (FFN weights prep fused into QKV launch)
    prep1<<<7180, 256>>>(E, Wq, Wk, Wv, bq, bk, bv, Eh, Wqkvth, bqkv);

    // QKV projection (+ z=1 aux: W1/W2 transposed f2h)
    hgemm2<2, false, false, false, true, true, false>
        <<<dim3(3072 / 128, NT / 128, 2), blk>>>(
        Eh, Wqkvth, bqkv, QKVh, 3072, DM, DM, DM, 1.f,
        W1, W2, W1th, W2th);

    // S = Q @ K^T / 32 (causal) (+ z=1 aux: Vth transpose)
    hgemm2<1, true, false, false, false, false, false>
        <<<dim3(NT / 128, NT / 128, 2), blk>>>(
        QKVh, QKVh + 1024, nullptr, S, NT, DM, 3072, 3072, 0.03125f,
        QKVh + 2048, nullptr, Vth, nullptr);

    softmax_causal<<<NT, 256>>>(S, Sh);

    // AE = probs @ V, split-K=2 balanced on the triangle -> AEd (2 slabs)
    hgemm2<0, false, true, false, false, false, true>
        <<<dim3(DM / 128, NT / 128, 2), blk>>>(
        Sh, Vth, nullptr, AEd, DM, NT, NT, NT, 1.f,
        nullptr, nullptr, nullptr, nullptr);

    add_layernorm<<<NT, 256>>>(AEd, AEd + (size_t)NT * DM, E, gamma, beta, Xh);

    // FFN
    hgemm2<0, false, false, true, true, true, false>
        <<<dim3(DF / 128, NT / 128, 1), blk>>>(
        Xh, W1th, b1, Hh, DF, DM, DM, DM, 1.f,
        nullptr, nullptr, nullptr, nullptr);
    hgemm2<0, false, false, false, true, false, false>
        <<<dim3(DM / 128, NT / 128, 1), blk>>>(
        Hh, W2th, b2, out, DM, DF, DF, DF, 1.f,
        nullptr, nullptr, nullptr, nullptr);
}